// round 6
// baseline (speedup 1.0000x reference)
#include <cuda_runtime.h>

#define BB 8192
#define HH 100
#define TT 512
#define NOPSN 5
#define ZW 400      // 4*H
#define EW 448      // padded width for emb@Wx rows (7*64)
#define RPW 7       // rows per warp
#define NWARP 8
#define RPB 56      // rows per block
#define NTHREADS 256

typedef unsigned long long u64t;

// Scratch (static device allocations are allowed)
__device__ float g_xW0[(size_t)BB * ZW];   // x0 @ W_x   [B,400]
__device__ float g_embW[6 * EW];           // emb @ W_x  [6,448] (cols >=400 zero)

__device__ __forceinline__ float tanha(float x) {
    float y;
    asm("tanh.approx.f32 %0, %1;" : "=f"(y) : "f"(x));
    return y;
}
__device__ __forceinline__ float fsig(float x) {
    return fmaf(0.5f, tanha(0.5f * x), 0.5f);
}
// packed fp32x2 FMA: d = a*b + c (elementwise on the two f32 halves)
__device__ __forceinline__ u64t ffma2(u64t a, u64t b, u64t c) {
    u64t d;
    asm("fma.rn.f32x2 %0, %1, %2, %3;" : "=l"(d) : "l"(a), "l"(b), "l"(c));
    return d;
}
__device__ __forceinline__ u64t pack2(float x) {
    unsigned int xi = __float_as_uint(x);
    u64t d;
    asm("mov.b64 %0, {%1, %2};" : "=l"(d) : "r"(xi), "r"(xi));
    return d;
}

__global__ void embW_kernel(const float* __restrict__ emb, const float* __restrict__ Wx) {
    int j = threadIdx.x;
    if (j >= EW) return;
    for (int e = 0; e < 6; ++e) {
        float acc = 0.f;
        if (j < ZW) {
            #pragma unroll 4
            for (int k = 0; k < HH; ++k)
                acc = fmaf(emb[e * HH + k], Wx[k * ZW + j], acc);
        }
        g_embW[e * EW + j] = acc;
    }
}

__global__ void xw0_kernel(const float* __restrict__ x0, const float* __restrict__ Wx) {
    __shared__ float xs[HH];
    int b = blockIdx.x;
    for (int i = threadIdx.x; i < HH; i += blockDim.x) xs[i] = x0[b * HH + i];
    __syncthreads();
    for (int j = threadIdx.x; j < ZW; j += blockDim.x) {
        float acc = 0.f;
        #pragma unroll 4
        for (int k = 0; k < HH; ++k) acc = fmaf(xs[k], Wx[k * ZW + j], acc);
        g_xW0[(size_t)b * ZW + j] = acc;
    }
}

__global__ void __launch_bounds__(NTHREADS, 1)
rnn_main(const float* __restrict__ Wh, const float* __restrict__ Wops,
         const float* __restrict__ u, float* __restrict__ out)
{
    extern __shared__ float sm[];
    float* sWh  = sm;                            // [100][400] unpadded
    float* sEmb = sWh + HH * ZW;                 // [6][448]
    u64t*  sH2  = (u64t*)(sEmb + 6 * EW);        // [56][100] (h,h) pairs (8B aligned: 170752 % 8 == 0)
    float* sZ   = (float*)(sH2 + RPB * HH);      // [8][400] per-warp z scratch

    const int tid = threadIdx.x, wid = tid >> 5, lane = tid & 31;

    for (int i = tid; i < HH * ZW; i += NTHREADS) sWh[i] = Wh[i];
    for (int i = tid; i < 6 * EW; i += NTHREADS)  sEmb[i] = g_embW[i];
    for (int i = tid; i < RPB * HH; i += NTHREADS) sH2[i] = 0ull;
    __syncthreads();

    // ---- anti-phase stagger: offset the partner warp on each SMSP by ~4k cyc.
    // No block-wide sync below, so the offset persists across all 512 steps,
    // letting one warp's FFMA2 mainloop cover the other's MUFU/reduce phase.
    if (wid & 4) {
        long long s0 = clock64();
        while (clock64() - s0 < 4000) { }
    }

    const int rowBlock = blockIdx.x * RPB;
    const int lrow0 = wid * RPW;           // first row (in block) for this warp
    const int gb0 = rowBlock + lrow0;      // first global row for this warp

    float cS[RPW][4];
    #pragma unroll
    for (int r = 0; r < RPW; ++r)
        #pragma unroll
        for (int s = 0; s < 4; ++s) cS[r][s] = 0.f;

    float wopsr[4][NOPSN];
    #pragma unroll
    for (int s = 0; s < 4; ++s) {
        int unit = lane + 32 * s;
        #pragma unroll
        for (int n = 0; n < NOPSN; ++n)
            wopsr[s][n] = (unit < HH) ? Wops[unit * NOPSN + n] : 0.f;
    }

    // per-lane scalars: lane r (<7) owns row gb0+r
    float accLP = 0.f, accENT = 0.f;
    int opReg = 0;

    for (int t = 0; t < TT; ++t) {
        // ---- prefetch gumbel inputs for this warp's 7 rows ----
        float un[NOPSN] = {0.f, 0.f, 0.f, 0.f, 0.f};
        {
            int b = gb0 + lane;
            if (lane < RPW && b < BB) {
                const float* up = u + ((size_t)t * BB + b) * NOPSN;
                #pragma unroll
                for (int n = 0; n < NOPSN; ++n) un[n] = up[n];
            }
        }

        // ---- init z accumulators (pairs: lane handles j = 2*lane + 64*s) ----
        u64t z[RPW][7];
        if (t == 0) {
            #pragma unroll
            for (int r = 0; r < RPW; ++r) {
                int bb = gb0 + r; if (bb >= BB) bb = BB - 1;
                const float* xp = g_xW0 + (size_t)bb * ZW;
                #pragma unroll
                for (int s = 0; s < 7; ++s) {
                    int j = 2 * lane + 64 * s;
                    z[r][s] = (j < ZW) ? *(const u64t*)(xp + j) : 0ull;
                }
            }
        } else {
            #pragma unroll
            for (int r = 0; r < RPW; ++r) {
                int orr = __shfl_sync(0xffffffffu, opReg, r);
                const float* ep = sEmb + orr * EW;
                #pragma unroll
                for (int s = 0; s < 7; ++s)
                    z[r][s] = *(const u64t*)(ep + 2 * lane + 64 * s);
            }
        }

        // ---- h @ W_h mainloop: 7 rows share every weight load, packed FMA ----
        const u64t* hRow = sH2 + lrow0 * HH;
        #pragma unroll 2
        for (int k = 0; k < HH; ++k) {
            u64t hp[RPW];
            #pragma unroll
            for (int r = 0; r < RPW; ++r)
                hp[r] = hRow[r * HH + k];            // LDS.64, broadcast
            const float* wrow = sWh + k * ZW + 2 * lane;
            #pragma unroll
            for (int s = 0; s < 7; ++s) {
                u64t w = *(const u64t*)(wrow + 64 * s);  // may over-read into sEmb pad; discarded lanes
                #pragma unroll
                for (int r = 0; r < RPW; ++r)
                    z[r][s] = ffma2(hp[r], w, z[r][s]);
            }
        }

        // ---- gates + logits per row ----
        float sums[NOPSN] = {0.f, 0.f, 0.f, 0.f, 0.f};
        float* zb = sZ + wid * ZW;

        #pragma unroll
        for (int r = 0; r < RPW; ++r) {
            #pragma unroll
            for (int s = 0; s < 7; ++s) {
                int j = 2 * lane + 64 * s;
                if (s < 6 || lane < 8) *(u64t*)(zb + j) = z[r][s];
            }
            __syncwarp();
            float pl[NOPSN] = {0.f, 0.f, 0.f, 0.f, 0.f};
            #pragma unroll
            for (int s2 = 0; s2 < 4; ++s2) {
                int unit = lane + 32 * s2;
                if (unit < HH) {
                    float zi = zb[unit];
                    float zf = zb[HH + unit];
                    float zc = zb[2 * HH + unit];
                    float zo = zb[3 * HH + unit];
                    float cn = fsig(zf) * cS[r][s2] + fsig(zi) * tanha(zc);
                    cS[r][s2] = cn;
                    float hn = fsig(zo) * tanha(cn);
                    sH2[(lrow0 + r) * HH + unit] = pack2(hn);
                    #pragma unroll
                    for (int n = 0; n < NOPSN; ++n)
                        pl[n] = fmaf(hn, wopsr[s2][n], pl[n]);
                }
            }
            __syncwarp();
            #pragma unroll
            for (int off = 16; off; off >>= 1) {
                #pragma unroll
                for (int n = 0; n < NOPSN; ++n)
                    pl[n] += __shfl_xor_sync(0xffffffffu, pl[n], off);
            }
            if (lane == r) {
                #pragma unroll
                for (int n = 0; n < NOPSN; ++n) sums[n] = pl[n];
            }
        }

        // ---- sampling / log-softmax epilogue (fast intrinsics) ----
        if (lane < RPW) {
            int b = gb0 + lane;
            if (b < BB) {
                float lg[NOPSN];
                #pragma unroll
                for (int n = 0; n < NOPSN; ++n) lg[n] = 1.5f * tanha(sums[n]);
                int op = 0;
                float best = 0.f, m = lg[0], lgsel = lg[0];
                #pragma unroll
                for (int n = 0; n < NOPSN; ++n) {
                    float gum = -__logf(-__logf(un[n] + 1e-9f) + 1e-9f);
                    float v = lg[n] + gum;
                    if (n == 0) { best = v; }
                    else if (v > best) { best = v; op = n; lgsel = lg[n]; }
                    if (lg[n] > m) m = lg[n];
                }
                float ssum = 0.f;
                #pragma unroll
                for (int n = 0; n < NOPSN; ++n) ssum += __expf(lg[n] - m);
                float lse = m + __logf(ssum);
                float cur = lse - lgsel;          // -log_softmax(logits)[op]
                float ent = cur * __expf(-cur);
                accLP += cur;
                accENT += ent;
                opReg = op;
                out[2 * (size_t)BB + (size_t)t * BB + b] = (float)op;
            }
        }
        __syncwarp();
    }

    if (lane < RPW) {
        int b = gb0 + lane;
        if (b < BB) {
            out[b] = accLP;
            out[BB + b] = accENT;
        }
    }
}

extern "C" void kernel_launch(void* const* d_in, const int* in_sizes, int n_in,
                              void* d_out, int out_size) {
    const float* x0  = (const float*)d_in[0];
    const float* Wx  = (const float*)d_in[1];
    const float* Wh  = (const float*)d_in[2];
    const float* Wop = (const float*)d_in[3];
    const float* emb = (const float*)d_in[4];
    const float* u   = (const float*)d_in[5];
    float* out = (float*)d_out;

    size_t smem = (size_t)(HH * ZW + 6 * EW) * sizeof(float)
                + (size_t)RPB * HH * sizeof(u64t)
                + (size_t)NWARP * ZW * sizeof(float);
    cudaFuncSetAttribute(rnn_main, cudaFuncAttributeMaxDynamicSharedMemorySize, (int)smem);

    embW_kernel<<<1, EW>>>(emb, Wx);
    xw0_kernel<<<BB, 128>>>(x0, Wx);
    int grid = (BB + RPB - 1) / RPB;   // 147 blocks, one wave on 148 SMs
    rnn_main<<<grid, NTHREADS, smem>>>(Wh, Wop, u, out);
}

// round 7
// speedup vs baseline: 1.6496x; 1.6496x over previous
#include <cuda_runtime.h>

#define BB 8192
#define HH 100
#define TT 512
#define NOPSN 5
#define ZW 400      // 4*H
#define EW 448      // padded width for emb@Wx rows (7*64)
#define RPW 7       // rows per warp
#define NWARP 8
#define RPB 56      // rows per block
#define NTHREADS 256

typedef unsigned long long u64t;

// Scratch (static device allocations are allowed)
__device__ float g_xW0[(size_t)BB * ZW];   // x0 @ W_x   [B,400]
__device__ float g_embW[6 * EW];           // emb @ W_x  [6,448] (cols >=400 zero)

__device__ __forceinline__ float tanha(float x) {
    float y;
    asm("tanh.approx.f32 %0, %1;" : "=f"(y) : "f"(x));
    return y;
}
__device__ __forceinline__ float fsig(float x) {
    return fmaf(0.5f, tanha(0.5f * x), 0.5f);
}
// packed fp32x2 FMA: d = a*b + c (elementwise on the two f32 halves)
__device__ __forceinline__ u64t ffma2(u64t a, u64t b, u64t c) {
    u64t d;
    asm("fma.rn.f32x2 %0, %1, %2, %3;" : "=l"(d) : "l"(a), "l"(b), "l"(c));
    return d;
}
// packed fp32x2 ADD (elementwise; bit-identical to two scalar adds)
__device__ __forceinline__ u64t addf2(u64t a, u64t b) {
    u64t d;
    asm("add.rn.f32x2 %0, %1, %2;" : "=l"(d) : "l"(a), "l"(b));
    return d;
}
__device__ __forceinline__ u64t pack2(float x) {
    unsigned int xi = __float_as_uint(x);
    u64t d;
    asm("mov.b64 %0, {%1, %2};" : "=l"(d) : "r"(xi), "r"(xi));
    return d;
}
__device__ __forceinline__ u64t pk2(float a, float b) {
    u64t d;
    asm("mov.b64 %0, {%1, %2};" : "=l"(d) : "r"(__float_as_uint(a)), "r"(__float_as_uint(b)));
    return d;
}
__device__ __forceinline__ void unpk(u64t v, float& lo, float& hi) {
    unsigned int a, b;
    asm("mov.b64 {%0, %1}, %2;" : "=r"(a), "=r"(b) : "l"(v));
    lo = __uint_as_float(a); hi = __uint_as_float(b);
}

__global__ void embW_kernel(const float* __restrict__ emb, const float* __restrict__ Wx) {
    int j = threadIdx.x;
    if (j >= EW) return;
    for (int e = 0; e < 6; ++e) {
        float acc = 0.f;
        if (j < ZW) {
            #pragma unroll 4
            for (int k = 0; k < HH; ++k)
                acc = fmaf(emb[e * HH + k], Wx[k * ZW + j], acc);
        }
        g_embW[e * EW + j] = acc;
    }
}

__global__ void xw0_kernel(const float* __restrict__ x0, const float* __restrict__ Wx) {
    __shared__ float xs[HH];
    int b = blockIdx.x;
    for (int i = threadIdx.x; i < HH; i += blockDim.x) xs[i] = x0[b * HH + i];
    __syncthreads();
    for (int j = threadIdx.x; j < ZW; j += blockDim.x) {
        float acc = 0.f;
        #pragma unroll 4
        for (int k = 0; k < HH; ++k) acc = fmaf(xs[k], Wx[k * ZW + j], acc);
        g_xW0[(size_t)b * ZW + j] = acc;
    }
}

__global__ void __launch_bounds__(NTHREADS, 1)
rnn_main(const float* __restrict__ Wh, const float* __restrict__ Wops,
         const float* __restrict__ u, float* __restrict__ out)
{
    extern __shared__ float sm[];
    float* sWh  = sm;                      // [100][400] unpadded
    float* sEmb = sWh + HH * ZW;           // [6][448]
    float* sH   = sEmb + 6 * EW;           // [56][100]
    float* sZ   = sH + RPB * HH;           // [8][400] per-warp z scratch

    const int tid = threadIdx.x, wid = tid >> 5, lane = tid & 31;

    for (int i = tid; i < HH * ZW; i += NTHREADS) sWh[i] = Wh[i];
    for (int i = tid; i < 6 * EW; i += NTHREADS)  sEmb[i] = g_embW[i];
    for (int i = tid; i < RPB * HH; i += NTHREADS) sH[i] = 0.f;
    __syncthreads();

    const int rowBlock = blockIdx.x * RPB;
    const int lrow0 = wid * RPW;           // first row (in block) for this warp
    const int gb0 = rowBlock + lrow0;      // first global row for this warp

    float cS[RPW][4];
    #pragma unroll
    for (int r = 0; r < RPW; ++r)
        #pragma unroll
        for (int s = 0; s < 4; ++s) cS[r][s] = 0.f;

    float wopsr[4][NOPSN];
    #pragma unroll
    for (int s = 0; s < 4; ++s) {
        int unit = lane + 32 * s;
        #pragma unroll
        for (int n = 0; n < NOPSN; ++n)
            wopsr[s][n] = (unit < HH) ? Wops[unit * NOPSN + n] : 0.f;
    }

    // per-lane scalars: lane r (<7) owns row gb0+r
    float accLP = 0.f, accENT = 0.f;
    int opReg = 0;

    const int j4 = 4 * lane;             // vector-group column base
    const int jt = 2 * lane + 384;       // tail column (valid when lane < 8)

    for (int t = 0; t < TT; ++t) {
        // ---- prefetch gumbel inputs for this warp's 7 rows ----
        float un[NOPSN] = {0.f, 0.f, 0.f, 0.f, 0.f};
        {
            int b = gb0 + lane;
            if (lane < RPW && b < BB) {
                const float* up = u + ((size_t)t * BB + b) * NOPSN;
                #pragma unroll
                for (int n = 0; n < NOPSN; ++n) un[n] = up[n];
            }
        }

        // ---- init z accumulators ----
        // groups g=0..2: lane covers j = 4*lane + 128*g (two packed pairs)
        // tail:          lane covers j = 2*lane + 384 (lanes >= 8 discarded)
        ulonglong2 z[RPW][3];
        u64t zt[RPW];
        if (t == 0) {
            #pragma unroll
            for (int r = 0; r < RPW; ++r) {
                int bb = gb0 + r; if (bb >= BB) bb = BB - 1;
                const float* xp = g_xW0 + (size_t)bb * ZW;
                #pragma unroll
                for (int g = 0; g < 3; ++g)
                    z[r][g] = *(const ulonglong2*)(xp + j4 + 128 * g);
                zt[r] = (jt < ZW) ? *(const u64t*)(xp + jt) : 0ull;
            }
        } else {
            #pragma unroll
            for (int r = 0; r < RPW; ++r) {
                int orr = __shfl_sync(0xffffffffu, opReg, r);
                const float* ep = sEmb + orr * EW;
                #pragma unroll
                for (int g = 0; g < 3; ++g)
                    z[r][g] = *(const ulonglong2*)(ep + j4 + 128 * g);
                zt[r] = *(const u64t*)(ep + jt);   // pad zone zeros; lanes>=8 discarded
            }
        }

        // ---- h @ W_h mainloop: 7 rows share every weight load, packed FMA ----
        #pragma unroll 2
        for (int k = 0; k < HH; ++k) {
            u64t hp[RPW];
            #pragma unroll
            for (int r = 0; r < RPW; ++r)
                hp[r] = pack2(sH[(lrow0 + r) * HH + k]);
            const float* wrow = sWh + k * ZW;
            #pragma unroll
            for (int g = 0; g < 3; ++g) {
                ulonglong2 w = *(const ulonglong2*)(wrow + j4 + 128 * g);   // LDS.128
                #pragma unroll
                for (int r = 0; r < RPW; ++r) {
                    z[r][g].x = ffma2(hp[r], w.x, z[r][g].x);
                    z[r][g].y = ffma2(hp[r], w.y, z[r][g].y);
                }
            }
            {
                u64t w = *(const u64t*)(wrow + jt);  // over-reads past row end for lanes>=8; discarded
                #pragma unroll
                for (int r = 0; r < RPW; ++r)
                    zt[r] = ffma2(hp[r], w, zt[r]);
            }
        }

        // ---- gates + logits per row ----
        float sums[NOPSN] = {0.f, 0.f, 0.f, 0.f, 0.f};
        float* zb = sZ + wid * ZW;

        #pragma unroll
        for (int r = 0; r < RPW; ++r) {
            #pragma unroll
            for (int g = 0; g < 3; ++g)
                *(ulonglong2*)(zb + j4 + 128 * g) = z[r][g];   // STS.128
            if (lane < 8) *(u64t*)(zb + jt) = zt[r];
            __syncwarp();
            float pl[NOPSN] = {0.f, 0.f, 0.f, 0.f, 0.f};
            #pragma unroll
            for (int s2 = 0; s2 < 4; ++s2) {
                int unit = lane + 32 * s2;
                if (unit < HH) {
                    float zi = zb[unit];
                    float zf = zb[HH + unit];
                    float zc = zb[2 * HH + unit];
                    float zo = zb[3 * HH + unit];
                    float cn = fsig(zf) * cS[r][s2] + fsig(zi) * tanha(zc);
                    cS[r][s2] = cn;
                    float hn = fsig(zo) * tanha(cn);
                    sH[(lrow0 + r) * HH + unit] = hn;
                    #pragma unroll
                    for (int n = 0; n < NOPSN; ++n)
                        pl[n] = fmaf(hn, wopsr[s2][n], pl[n]);
                }
            }
            __syncwarp();
            // packed butterfly: (pl0,pl1),(pl2,pl3) in f32x2, pl4 scalar — bit-identical adds
            u64t P01 = pk2(pl[0], pl[1]);
            u64t P23 = pk2(pl[2], pl[3]);
            float p4 = pl[4];
            #pragma unroll
            for (int off = 16; off; off >>= 1) {
                P01 = addf2(P01, __shfl_xor_sync(0xffffffffu, P01, off));
                P23 = addf2(P23, __shfl_xor_sync(0xffffffffu, P23, off));
                p4 += __shfl_xor_sync(0xffffffffu, p4, off);
            }
            if (lane == r) {
                unpk(P01, sums[0], sums[1]);
                unpk(P23, sums[2], sums[3]);
                sums[4] = p4;
            }
        }

        // ---- sampling / log-softmax epilogue (fast intrinsics) ----
        if (lane < RPW) {
            int b = gb0 + lane;
            if (b < BB) {
                float lg[NOPSN];
                #pragma unroll
                for (int n = 0; n < NOPSN; ++n) lg[n] = 1.5f * tanha(sums[n]);
                int op = 0;
                float best = 0.f, m = lg[0], lgsel = lg[0];
                #pragma unroll
                for (int n = 0; n < NOPSN; ++n) {
                    float gum = -__logf(-__logf(un[n] + 1e-9f) + 1e-9f);
                    float v = lg[n] + gum;
                    if (n == 0) { best = v; }
                    else if (v > best) { best = v; op = n; lgsel = lg[n]; }
                    if (lg[n] > m) m = lg[n];
                }
                float ssum = 0.f;
                #pragma unroll
                for (int n = 0; n < NOPSN; ++n) ssum += __expf(lg[n] - m);
                float lse = m + __logf(ssum);
                float cur = lse - lgsel;          // -log_softmax(logits)[op]
                float ent = cur * __expf(-cur);
                accLP += cur;
                accENT += ent;
                opReg = op;
                out[2 * (size_t)BB + (size_t)t * BB + b] = (float)op;
            }
        }
        __syncwarp();
    }

    if (lane < RPW) {
        int b = gb0 + lane;
        if (b < BB) {
            out[b] = accLP;
            out[BB + b] = accENT;
        }
    }
}

extern "C" void kernel_launch(void* const* d_in, const int* in_sizes, int n_in,
                              void* d_out, int out_size) {
    const float* x0  = (const float*)d_in[0];
    const float* Wx  = (const float*)d_in[1];
    const float* Wh  = (const float*)d_in[2];
    const float* Wop = (const float*)d_in[3];
    const float* emb = (const float*)d_in[4];
    const float* u   = (const float*)d_in[5];
    float* out = (float*)d_out;

    size_t smem = (size_t)(HH * ZW + 6 * EW + RPB * HH + NWARP * ZW) * sizeof(float);
    cudaFuncSetAttribute(rnn_main, cudaFuncAttributeMaxDynamicSharedMemorySize, (int)smem);

    embW_kernel<<<1, EW>>>(emb, Wx);
    xw0_kernel<<<BB, 128>>>(x0, Wx);
    int grid = (BB + RPB - 1) / RPB;   // 147 blocks, one wave on 148 SMs
    rnn_main<<<grid, NTHREADS, smem>>>(Wh, Wop, u, out);
}

// round 8
// speedup vs baseline: 1.9479x; 1.1808x over previous
#include <cuda_runtime.h>

#define BB 8192
#define HH 100
#define TT 512
#define NOPSN 5
#define ZW 400      // 4*H
#define EW 448      // padded width for emb@Wx rows (7*64)
#define RPW 7       // rows per warp
#define NWARP 8
#define RPB 56      // rows per block
#define NTHREADS 256

typedef unsigned long long u64t;

// Scratch (static device allocations are allowed)
__device__ float g_xW0[(size_t)BB * ZW];   // x0 @ W_x   [B,400]
__device__ float g_embW[6 * EW];           // emb @ W_x  [6,448] (cols >=400 zero)

__device__ __forceinline__ float tanha(float x) {
    float y;
    asm("tanh.approx.f32 %0, %1;" : "=f"(y) : "f"(x));
    return y;
}
__device__ __forceinline__ float fsig(float x) {
    return fmaf(0.5f, tanha(0.5f * x), 0.5f);
}
// packed fp32x2 FMA: d = a*b + c (elementwise on the two f32 halves)
__device__ __forceinline__ u64t ffma2(u64t a, u64t b, u64t c) {
    u64t d;
    asm("fma.rn.f32x2 %0, %1, %2, %3;" : "=l"(d) : "l"(a), "l"(b), "l"(c));
    return d;
}
// packed fp32x2 ADD (elementwise; bit-identical to two scalar adds)
__device__ __forceinline__ u64t addf2(u64t a, u64t b) {
    u64t d;
    asm("add.rn.f32x2 %0, %1, %2;" : "=l"(d) : "l"(a), "l"(b));
    return d;
}
__device__ __forceinline__ u64t pack2(float x) {
    unsigned int xi = __float_as_uint(x);
    u64t d;
    asm("mov.b64 %0, {%1, %2};" : "=l"(d) : "r"(xi), "r"(xi));
    return d;
}
__device__ __forceinline__ u64t pk2(float a, float b) {
    u64t d;
    asm("mov.b64 %0, {%1, %2};" : "=l"(d) : "r"(__float_as_uint(a)), "r"(__float_as_uint(b)));
    return d;
}
__device__ __forceinline__ void unpk(u64t v, float& lo, float& hi) {
    unsigned int a, b;
    asm("mov.b64 {%0, %1}, %2;" : "=r"(a), "=r"(b) : "l"(v));
    lo = __uint_as_float(a); hi = __uint_as_float(b);
}

__global__ void embW_kernel(const float* __restrict__ emb, const float* __restrict__ Wx) {
    int j = threadIdx.x;
    if (j >= EW) return;
    for (int e = 0; e < 6; ++e) {
        float acc = 0.f;
        if (j < ZW) {
            #pragma unroll 4
            for (int k = 0; k < HH; ++k)
                acc = fmaf(emb[e * HH + k], Wx[k * ZW + j], acc);
        }
        g_embW[e * EW + j] = acc;
    }
}

__global__ void xw0_kernel(const float* __restrict__ x0, const float* __restrict__ Wx) {
    __shared__ float xs[HH];
    int b = blockIdx.x;
    for (int i = threadIdx.x; i < HH; i += blockDim.x) xs[i] = x0[b * HH + i];
    __syncthreads();
    for (int j = threadIdx.x; j < ZW; j += blockDim.x) {
        float acc = 0.f;
        #pragma unroll 4
        for (int k = 0; k < HH; ++k) acc = fmaf(xs[k], Wx[k * ZW + j], acc);
        g_xW0[(size_t)b * ZW + j] = acc;
    }
}

__global__ void __launch_bounds__(NTHREADS, 1)
rnn_main(const float* __restrict__ Wh, const float* __restrict__ Wops,
         const float* __restrict__ u, float* __restrict__ out)
{
    extern __shared__ float sm[];
    float* sWh  = sm;                      // [100][400] unpadded
    float* sEmb = sWh + HH * ZW;           // [6][448]
    float* sH   = sEmb + 6 * EW;           // [56][100]
    float* sZ   = sH + RPB * HH;           // [8][400] per-warp z scratch

    const int tid = threadIdx.x, wid = tid >> 5, lane = tid & 31;

    for (int i = tid; i < HH * ZW; i += NTHREADS) sWh[i] = Wh[i];
    for (int i = tid; i < 6 * EW; i += NTHREADS)  sEmb[i] = g_embW[i];
    for (int i = tid; i < RPB * HH; i += NTHREADS) sH[i] = 0.f;
    __syncthreads();

    // ---- anti-phase stagger: offset SMSP-partner warps by ~4k cyc (one-time).
    // No block-wide sync inside the t-loop, so the offset persists and one
    // warp's FFMA2 mainloop covers the other's MUFU/gate/reduce phase.
    if (wid & 4) {
        long long s0 = clock64();
        while (clock64() - s0 < 4000) { }
    }

    const int rowBlock = blockIdx.x * RPB;
    const int lrow0 = wid * RPW;           // first row (in block) for this warp
    const int gb0 = rowBlock + lrow0;      // first global row for this warp

    float cS[RPW][4];
    #pragma unroll
    for (int r = 0; r < RPW; ++r)
        #pragma unroll
        for (int s = 0; s < 4; ++s) cS[r][s] = 0.f;

    float wopsr[4][NOPSN];
    #pragma unroll
    for (int s = 0; s < 4; ++s) {
        int unit = lane + 32 * s;
        #pragma unroll
        for (int n = 0; n < NOPSN; ++n)
            wopsr[s][n] = (unit < HH) ? Wops[unit * NOPSN + n] : 0.f;
    }

    // per-lane scalars: lane r (<7) owns row gb0+r
    float accLP = 0.f, accENT = 0.f;
    int opReg = 0;

    for (int t = 0; t < TT; ++t) {
        // ---- prefetch gumbel inputs for this warp's 7 rows ----
        float un[NOPSN] = {0.f, 0.f, 0.f, 0.f, 0.f};
        {
            int b = gb0 + lane;
            if (lane < RPW && b < BB) {
                const float* up = u + ((size_t)t * BB + b) * NOPSN;
                #pragma unroll
                for (int n = 0; n < NOPSN; ++n) un[n] = up[n];
            }
        }

        // ---- init z accumulators (pairs: lane handles j = 2*lane + 64*s) ----
        u64t z[RPW][7];
        if (t == 0) {
            #pragma unroll
            for (int r = 0; r < RPW; ++r) {
                int bb = gb0 + r; if (bb >= BB) bb = BB - 1;
                const float* xp = g_xW0 + (size_t)bb * ZW;
                #pragma unroll
                for (int s = 0; s < 7; ++s) {
                    int j = 2 * lane + 64 * s;
                    z[r][s] = (j < ZW) ? *(const u64t*)(xp + j) : 0ull;
                }
            }
        } else {
            #pragma unroll
            for (int r = 0; r < RPW; ++r) {
                int orr = __shfl_sync(0xffffffffu, opReg, r);
                const float* ep = sEmb + orr * EW;
                #pragma unroll
                for (int s = 0; s < 7; ++s)
                    z[r][s] = *(const u64t*)(ep + 2 * lane + 64 * s);
            }
        }

        // ---- h @ W_h mainloop: 7 rows share every weight load, packed FMA ----
        // (FROZEN: this exact shape is what ptxas pairs into clean FFMA2 streams)
        #pragma unroll 2
        for (int k = 0; k < HH; ++k) {
            u64t hp[RPW];
            #pragma unroll
            for (int r = 0; r < RPW; ++r)
                hp[r] = pack2(sH[(lrow0 + r) * HH + k]);
            const float* wrow = sWh + k * ZW + 2 * lane;
            #pragma unroll
            for (int s = 0; s < 7; ++s) {
                u64t w = *(const u64t*)(wrow + 64 * s);  // may over-read into sEmb pad; discarded lanes
                #pragma unroll
                for (int r = 0; r < RPW; ++r)
                    z[r][s] = ffma2(hp[r], w, z[r][s]);
            }
        }

        // ---- gates + logits per row ----
        float sums[NOPSN] = {0.f, 0.f, 0.f, 0.f, 0.f};
        float* zb = sZ + wid * ZW;

        #pragma unroll
        for (int r = 0; r < RPW; ++r) {
            #pragma unroll
            for (int s = 0; s < 7; ++s) {
                int j = 2 * lane + 64 * s;
                if (s < 6 || lane < 8) *(u64t*)(zb + j) = z[r][s];
            }
            __syncwarp();
            float pl[NOPSN] = {0.f, 0.f, 0.f, 0.f, 0.f};
            #pragma unroll
            for (int s2 = 0; s2 < 4; ++s2) {
                int unit = lane + 32 * s2;
                if (unit < HH) {
                    float zi = zb[unit];
                    float zf = zb[HH + unit];
                    float zc = zb[2 * HH + unit];
                    float zo = zb[3 * HH + unit];
                    float cn = fsig(zf) * cS[r][s2] + fsig(zi) * tanha(zc);
                    cS[r][s2] = cn;
                    float hn = fsig(zo) * tanha(cn);
                    sH[(lrow0 + r) * HH + unit] = hn;
                    #pragma unroll
                    for (int n = 0; n < NOPSN; ++n)
                        pl[n] = fmaf(hn, wopsr[s2][n], pl[n]);
                }
            }
            __syncwarp();
            // packed butterfly: (pl0,pl1),(pl2,pl3) in f32x2, pl4 scalar — bit-identical adds
            u64t P01 = pk2(pl[0], pl[1]);
            u64t P23 = pk2(pl[2], pl[3]);
            float p4 = pl[4];
            #pragma unroll
            for (int off = 16; off; off >>= 1) {
                P01 = addf2(P01, __shfl_xor_sync(0xffffffffu, P01, off));
                P23 = addf2(P23, __shfl_xor_sync(0xffffffffu, P23, off));
                p4 += __shfl_xor_sync(0xffffffffu, p4, off);
            }
            if (lane == r) {
                unpk(P01, sums[0], sums[1]);
                unpk(P23, sums[2], sums[3]);
                sums[4] = p4;
            }
        }

        // ---- sampling / log-softmax epilogue (fast intrinsics) ----
        if (lane < RPW) {
            int b = gb0 + lane;
            if (b < BB) {
                float lg[NOPSN];
                #pragma unroll
                for (int n = 0; n < NOPSN; ++n) lg[n] = 1.5f * tanha(sums[n]);
                int op = 0;
                float best = 0.f, m = lg[0], lgsel = lg[0];
                #pragma unroll
                for (int n = 0; n < NOPSN; ++n) {
                    float gum = -__logf(-__logf(un[n] + 1e-9f) + 1e-9f);
                    float v = lg[n] + gum;
                    if (n == 0) { best = v; }
                    else if (v > best) { best = v; op = n; lgsel = lg[n]; }
                    if (lg[n] > m) m = lg[n];
                }
                float ssum = 0.f;
                #pragma unroll
                for (int n = 0; n < NOPSN; ++n) ssum += __expf(lg[n] - m);
                float lse = m + __logf(ssum);
                float cur = lse - lgsel;          // -log_softmax(logits)[op]
                float ent = cur * __expf(-cur);
                accLP += cur;
                accENT += ent;
                opReg = op;
                out[2 * (size_t)BB + (size_t)t * BB + b] = (float)op;
            }
        }
        __syncwarp();
    }

    if (lane < RPW) {
        int b = gb0 + lane;
        if (b < BB) {
            out[b] = accLP;
            out[BB + b] = accENT;
        }
    }
}

extern "C" void kernel_launch(void* const* d_in, const int* in_sizes, int n_in,
                              void* d_out, int out_size) {
    const float* x0  = (const float*)d_in[0];
    const float* Wx  = (const float*)d_in[1];
    const float* Wh  = (const float*)d_in[2];
    const float* Wop = (const float*)d_in[3];
    const float* emb = (const float*)d_in[4];
    const float* u   = (const float*)d_in[5];
    float* out = (float*)d_out;

    size_t smem = (size_t)(HH * ZW + 6 * EW + RPB * HH + NWARP * ZW) * sizeof(float);
    cudaFuncSetAttribute(rnn_main, cudaFuncAttributeMaxDynamicSharedMemorySize, (int)smem);

    embW_kernel<<<1, EW>>>(emb, Wx);
    xw0_kernel<<<BB, 128>>>(x0, Wx);
    int grid = (BB + RPB - 1) / RPB;   // 147 blocks, one wave on 148 SMs
    rnn_main<<<grid, NTHREADS, smem>>>(Wh, Wop, u, out);
}

// round 9
// speedup vs baseline: 1.9486x; 1.0003x over previous
#include <cuda_runtime.h>

#define BB 8192
#define HH 100
#define TT 512
#define NOPSN 5
#define ZW 400      // 4*H
#define EW 448      // padded width for emb@Wx rows (7*64)
#define RPW 7       // rows per warp
#define NWARP 8
#define RPB 56      // rows per block
#define NTHREADS 256

typedef unsigned long long u64t;

// Scratch (static device allocations are allowed)
__device__ float g_xW0[(size_t)BB * ZW];   // x0 @ W_x   [B,400]
__device__ float g_embW[6 * EW];           // emb @ W_x  [6,448] (cols >=400 zero)

__device__ __forceinline__ float tanha(float x) {
    float y;
    asm("tanh.approx.f32 %0, %1;" : "=f"(y) : "f"(x));
    return y;
}
__device__ __forceinline__ float fsig(float x) {
    return fmaf(0.5f, tanha(0.5f * x), 0.5f);
}
// packed fp32x2 FMA: d = a*b + c (elementwise on the two f32 halves)
__device__ __forceinline__ u64t ffma2(u64t a, u64t b, u64t c) {
    u64t d;
    asm("fma.rn.f32x2 %0, %1, %2, %3;" : "=l"(d) : "l"(a), "l"(b), "l"(c));
    return d;
}
// packed fp32x2 ADD (elementwise; bit-identical to two scalar adds)
__device__ __forceinline__ u64t addf2(u64t a, u64t b) {
    u64t d;
    asm("add.rn.f32x2 %0, %1, %2;" : "=l"(d) : "l"(a), "l"(b));
    return d;
}
__device__ __forceinline__ u64t pack2(float x) {
    unsigned int xi = __float_as_uint(x);
    u64t d;
    asm("mov.b64 %0, {%1, %2};" : "=l"(d) : "r"(xi), "r"(xi));
    return d;
}
__device__ __forceinline__ u64t pk2(float a, float b) {
    u64t d;
    asm("mov.b64 %0, {%1, %2};" : "=l"(d) : "r"(__float_as_uint(a)), "r"(__float_as_uint(b)));
    return d;
}
__device__ __forceinline__ void unpk(u64t v, float& lo, float& hi) {
    unsigned int a, b;
    asm("mov.b64 {%0, %1}, %2;" : "=r"(a), "=r"(b) : "l"(v));
    lo = __uint_as_float(a); hi = __uint_as_float(b);
}

__global__ void embW_kernel(const float* __restrict__ emb, const float* __restrict__ Wx) {
    int j = threadIdx.x;
    if (j >= EW) return;
    for (int e = 0; e < 6; ++e) {
        float acc = 0.f;
        if (j < ZW) {
            #pragma unroll 4
            for (int k = 0; k < HH; ++k)
                acc = fmaf(emb[e * HH + k], Wx[k * ZW + j], acc);
        }
        g_embW[e * EW + j] = acc;
    }
}

__global__ void xw0_kernel(const float* __restrict__ x0, const float* __restrict__ Wx) {
    __shared__ float xs[HH];
    int b = blockIdx.x;
    for (int i = threadIdx.x; i < HH; i += blockDim.x) xs[i] = x0[b * HH + i];
    __syncthreads();
    for (int j = threadIdx.x; j < ZW; j += blockDim.x) {
        float acc = 0.f;
        #pragma unroll 4
        for (int k = 0; k < HH; ++k) acc = fmaf(xs[k], Wx[k * ZW + j], acc);
        g_xW0[(size_t)b * ZW + j] = acc;
    }
}

__global__ void __launch_bounds__(NTHREADS, 1)
rnn_main(const float* __restrict__ Wh, const float* __restrict__ Wops,
         const float* __restrict__ u, float* __restrict__ out)
{
    extern __shared__ float sm[];
    float* sWh  = sm;                      // [100][400] unpadded
    float* sEmb = sWh + HH * ZW;           // [6][448]
    float* sH   = sEmb + 6 * EW;           // [56][100]
    float* sZ   = sH + RPB * HH;           // [8][400] per-warp z scratch

    const int tid = threadIdx.x, wid = tid >> 5, lane = tid & 31;

    for (int i = tid; i < HH * ZW; i += NTHREADS) sWh[i] = Wh[i];
    for (int i = tid; i < 6 * EW; i += NTHREADS)  sEmb[i] = g_embW[i];
    for (int i = tid; i < RPB * HH; i += NTHREADS) sH[i] = 0.f;
    __syncthreads();

    // ---- anti-phase stagger: offset SMSP-partner warps by ~4k cyc (one-time).
    // No block-wide sync inside the t-loop, so the offset persists and one
    // warp's FFMA2 mainloop covers the other's MUFU/gate/reduce phase.
    if (wid & 4) {
        long long s0 = clock64();
        while (clock64() - s0 < 4000) { }
    }

    const int rowBlock = blockIdx.x * RPB;
    const int lrow0 = wid * RPW;           // first row (in block) for this warp
    const int gb0 = rowBlock + lrow0;      // first global row for this warp

    float cS[RPW][4];
    #pragma unroll
    for (int r = 0; r < RPW; ++r)
        #pragma unroll
        for (int s = 0; s < 4; ++s) cS[r][s] = 0.f;

    float wopsr[4][NOPSN];
    #pragma unroll
    for (int s = 0; s < 4; ++s) {
        int unit = lane + 32 * s;
        #pragma unroll
        for (int n = 0; n < NOPSN; ++n)
            wopsr[s][n] = (unit < HH) ? Wops[unit * NOPSN + n] : 0.f;
    }

    // per-lane scalars: lane r (<7) owns row gb0+r
    float accLP = 0.f, accENT = 0.f;
    int opReg = 0;

    for (int t = 0; t < TT; ++t) {
        // ---- prefetch gumbel inputs for this warp's 7 rows ----
        float un[NOPSN] = {0.f, 0.f, 0.f, 0.f, 0.f};
        {
            int b = gb0 + lane;
            if (lane < RPW && b < BB) {
                const float* up = u + ((size_t)t * BB + b) * NOPSN;
                #pragma unroll
                for (int n = 0; n < NOPSN; ++n) un[n] = up[n];
            }
        }

        // ---- init z accumulators (pairs: lane handles j = 2*lane + 64*s) ----
        u64t z[RPW][7];
        if (t == 0) {
            #pragma unroll
            for (int r = 0; r < RPW; ++r) {
                int bb = gb0 + r; if (bb >= BB) bb = BB - 1;
                const float* xp = g_xW0 + (size_t)bb * ZW;
                #pragma unroll
                for (int s = 0; s < 7; ++s) {
                    int j = 2 * lane + 64 * s;
                    z[r][s] = (j < ZW) ? *(const u64t*)(xp + j) : 0ull;
                }
            }
        } else {
            #pragma unroll
            for (int r = 0; r < RPW; ++r) {
                int orr = __shfl_sync(0xffffffffu, opReg, r);
                const float* ep = sEmb + orr * EW;
                #pragma unroll
                for (int s = 0; s < 7; ++s)
                    z[r][s] = *(const u64t*)(ep + 2 * lane + 64 * s);
            }
        }

        // ---- h @ W_h mainloop: 7 rows share every weight load, packed FMA ----
        // (FROZEN: this exact shape is what ptxas pairs into clean FFMA2 streams)
        #pragma unroll 2
        for (int k = 0; k < HH; ++k) {
            u64t hp[RPW];
            #pragma unroll
            for (int r = 0; r < RPW; ++r)
                hp[r] = pack2(sH[(lrow0 + r) * HH + k]);
            const float* wrow = sWh + k * ZW + 2 * lane;
            #pragma unroll
            for (int s = 0; s < 7; ++s) {
                u64t w = *(const u64t*)(wrow + 64 * s);  // may over-read into sEmb pad; discarded lanes
                #pragma unroll
                for (int r = 0; r < RPW; ++r)
                    z[r][s] = ffma2(hp[r], w, z[r][s]);
            }
        }

        // ---- gates + logits per row ----
        float sums[NOPSN] = {0.f, 0.f, 0.f, 0.f, 0.f};
        float* zb = sZ + wid * ZW;

        #pragma unroll
        for (int r = 0; r < RPW; ++r) {
            #pragma unroll
            for (int s = 0; s < 7; ++s) {
                int j = 2 * lane + 64 * s;
                if (s < 6 || lane < 8) *(u64t*)(zb + j) = z[r][s];
            }
            __syncwarp();
            float pl[NOPSN] = {0.f, 0.f, 0.f, 0.f, 0.f};
            #pragma unroll
            for (int s2 = 0; s2 < 4; ++s2) {
                int unit = lane + 32 * s2;
                if (unit < HH) {
                    float zi = zb[unit];
                    float zf = zb[HH + unit];
                    float zc = zb[2 * HH + unit];
                    float zo = zb[3 * HH + unit];
                    float cn = fsig(zf) * cS[r][s2] + fsig(zi) * tanha(zc);
                    cS[r][s2] = cn;
                    float hn = fsig(zo) * tanha(cn);
                    sH[(lrow0 + r) * HH + unit] = hn;
                    #pragma unroll
                    for (int n = 0; n < NOPSN; ++n)
                        pl[n] = fmaf(hn, wopsr[s2][n], pl[n]);
                }
            }
            __syncwarp();
            // packed butterfly: (pl0,pl1),(pl2,pl3) in f32x2, pl4 scalar — bit-identical adds
            u64t P01 = pk2(pl[0], pl[1]);
            u64t P23 = pk2(pl[2], pl[3]);
            float p4 = pl[4];
            #pragma unroll
            for (int off = 16; off; off >>= 1) {
                P01 = addf2(P01, __shfl_xor_sync(0xffffffffu, P01, off));
                P23 = addf2(P23, __shfl_xor_sync(0xffffffffu, P23, off));
                p4 += __shfl_xor_sync(0xffffffffu, p4, off);
            }
            if (lane == r) {
                unpk(P01, sums[0], sums[1]);
                unpk(P23, sums[2], sums[3]);
                sums[4] = p4;
            }
        }

        // ---- sampling / log-softmax epilogue (fast intrinsics) ----
        if (lane < RPW) {
            int b = gb0 + lane;
            if (b < BB) {
                float lg[NOPSN];
                #pragma unroll
                for (int n = 0; n < NOPSN; ++n) lg[n] = 1.5f * tanha(sums[n]);
                int op = 0;
                float best = 0.f, m = lg[0], lgsel = lg[0];
                #pragma unroll
                for (int n = 0; n < NOPSN; ++n) {
                    float gum = -__logf(-__logf(un[n] + 1e-9f) + 1e-9f);
                    float v = lg[n] + gum;
                    if (n == 0) { best = v; }
                    else if (v > best) { best = v; op = n; lgsel = lg[n]; }
                    if (lg[n] > m) m = lg[n];
                }
                float ssum = 0.f;
                #pragma unroll
                for (int n = 0; n < NOPSN; ++n) ssum += __expf(lg[n] - m);
                float lse = m + __logf(ssum);
                float cur = lse - lgsel;          // -log_softmax(logits)[op]
                float ent = cur * __expf(-cur);
                accLP += cur;
                accENT += ent;
                opReg = op;
                out[2 * (size_t)BB + (size_t)t * BB + b] = (float)op;
            }
        }
        __syncwarp();
    }

    if (lane < RPW) {
        int b = gb0 + lane;
        if (b < BB) {
            out[b] = accLP;
            out[BB + b] = accENT;
        }
    }
}

extern "C" void kernel_launch(void* const* d_in, const int* in_sizes, int n_in,
                              void* d_out, int out_size) {
    const float* x0  = (const float*)d_in[0];
    const float* Wx  = (const float*)d_in[1];
    const float* Wh  = (const float*)d_in[2];
    const float* Wop = (const float*)d_in[3];
    const float* emb = (const float*)d_in[4];
    const float* u   = (const float*)d_in[5];
    float* out = (float*)d_out;

    size_t smem = (size_t)(HH * ZW + 6 * EW + RPB * HH + NWARP * ZW) * sizeof(float);
    cudaFuncSetAttribute(rnn_main, cudaFuncAttributeMaxDynamicSharedMemorySize, (int)smem);

    embW_kernel<<<1, EW>>>(emb, Wx);
    xw0_kernel<<<BB, 128>>>(x0, Wx);
    int grid = (BB + RPB - 1) / RPB;   // 147 blocks, one wave on 148 SMs
    rnn_main<<<grid, NTHREADS, smem>>>(Wh, Wop, u, out);
}

// round 11
// speedup vs baseline: 3.2434x; 1.6645x over previous
#include <cuda_runtime.h>
#include <cuda_fp16.h>
#include <cstdint>

#define BB 8192
#define HH 100
#define TT 512
#define NOPSN 5
#define ZW 400
#define MROWS 64
#define NTHREADS 256
#define RSTRIDE 464   // bytes/row: 112 f16 hi (224B) + 112 f16 lo (224B) + 16B pad

// smem byte offsets
#define SM_B    0                  // WhT hi/lo  [400][RSTRIDE]   = 185600
#define SM_A    185600             // h stage    [64][RSTRIDE]    = 29696
#define SM_EMB  215296             // float[6*400]                = 9600
#define SM_WOPS 224896             // float[500]                  = 2000
#define SM_PL   226896             // float[64*10]                = 2560
#define SM_OPS  229456             // int[64]                     = 256
#define SM_TOTAL 229712

__device__ float g_xW0[(size_t)BB * ZW];   // x0@Wx, permuted cols
__device__ float g_embW[6 * ZW];           // emb@Wx, permuted cols

// storage col j -> original col (j%4)*100 + j/4 (gate-interleaved)
__device__ __host__ __forceinline__ int permCol(int j) { return (j & 3) * 100 + (j >> 2); }

__device__ __forceinline__ float tanha(float x) {
    float y; asm("tanh.approx.f32 %0, %1;" : "=f"(y) : "f"(x)); return y;
}
__device__ __forceinline__ float fsig(float x) { return fmaf(0.5f, tanha(0.5f * x), 0.5f); }

__device__ __forceinline__ uint32_t smem_u32(const void* p) {
    uint32_t a;
    asm("{ .reg .u64 t; cvta.to.shared.u64 t, %1; cvt.u32.u64 %0, t; }" : "=r"(a) : "l"(p));
    return a;
}
__device__ __forceinline__ void ldsm4(uint32_t& r0, uint32_t& r1, uint32_t& r2, uint32_t& r3, uint32_t a) {
    asm volatile("ldmatrix.sync.aligned.m8n8.x4.shared.b16 {%0,%1,%2,%3}, [%4];"
                 : "=r"(r0), "=r"(r1), "=r"(r2), "=r"(r3) : "r"(a));
}
__device__ __forceinline__ void mma16816(float& d0, float& d1, float& d2, float& d3,
                                         uint32_t a0, uint32_t a1, uint32_t a2, uint32_t a3,
                                         uint32_t b0, uint32_t b1) {
    asm volatile("mma.sync.aligned.m16n8k16.row.col.f32.f16.f16.f32 "
                 "{%0,%1,%2,%3}, {%4,%5,%6,%7}, {%8,%9}, {%0,%1,%2,%3};"
                 : "+f"(d0), "+f"(d1), "+f"(d2), "+f"(d3)
                 : "r"(a0), "r"(a1), "r"(a2), "r"(a3), "r"(b0), "r"(b1));
}

__global__ void embW_kernel(const float* __restrict__ emb, const float* __restrict__ Wx) {
    int j = threadIdx.x;
    if (j >= ZW) return;
    int pj = permCol(j);
    for (int e = 0; e < 6; ++e) {
        float acc = 0.f;
        #pragma unroll 4
        for (int k = 0; k < HH; ++k) acc = fmaf(emb[e * HH + k], Wx[k * ZW + pj], acc);
        g_embW[e * ZW + j] = acc;
    }
}

__global__ void xw0_kernel(const float* __restrict__ x0, const float* __restrict__ Wx) {
    __shared__ float xs[HH];
    int b = blockIdx.x;
    for (int i = threadIdx.x; i < HH; i += blockDim.x) xs[i] = x0[b * HH + i];
    __syncthreads();
    for (int j = threadIdx.x; j < ZW; j += blockDim.x) {
        int pj = permCol(j);
        float acc = 0.f;
        #pragma unroll 4
        for (int k = 0; k < HH; ++k) acc = fmaf(xs[k], Wx[k * ZW + pj], acc);
        g_xW0[(size_t)b * ZW + j] = acc;
    }
}

__global__ void __launch_bounds__(NTHREADS, 1)
rnn_main(const float* __restrict__ Wh, const float* __restrict__ Wops,
         const float* __restrict__ upt, float* __restrict__ out)
{
    extern __shared__ char smb[];
    const uint32_t sb = smem_u32(smb);
    float* sEmbF = (float*)(smb + SM_EMB);
    float* sWops = (float*)(smb + SM_WOPS);
    float* sPL   = (float*)(smb + SM_PL);
    int*   sOps  = (int*)(smb + SM_OPS);

    const int tid = threadIdx.x, wid = tid >> 5, lane = tid & 31;

    // ---- one-time init: B = Wh^T as f16 hi/lo, gate-interleaved n, K padded to 112 ----
    for (int idx = tid; idx < 400 * 112; idx += NTHREADS) {
        int n = idx / 112, k = idx - n * 112;
        float w = (k < HH) ? Wh[k * ZW + permCol(n)] : 0.f;
        __half hh = __float2half_rn(w);
        __half hl = __float2half_rn(w - __half2float(hh));
        *(__half*)(smb + SM_B + n * RSTRIDE + k * 2) = hh;
        *(__half*)(smb + SM_B + n * RSTRIDE + 224 + k * 2) = hl;
    }
    // zero A stage (h(-1) = 0, incl. k-pad 100..111)
    for (int i = tid; i < (MROWS * RSTRIDE) / 4; i += NTHREADS)
        ((uint32_t*)(smb + SM_A))[i] = 0u;
    for (int i = tid; i < 6 * ZW; i += NTHREADS) sEmbF[i] = g_embW[i];
    for (int i = tid; i < HH * NOPSN; i += NTHREADS) sWops[i] = Wops[i];
    __syncthreads();

    const int mt = wid & 3, nh = wid >> 2;
    const int gr = lane >> 2, cq = lane & 3;
    const bool even = ((lane & 1) == 0);
    const int m0 = mt * 16;
    const int R0l = m0 + gr, R1l = R0l + 8;
    const int jbase = nh * 25;

    // A-frag lane addressing (ldmatrix x4 groups)
    const int lr = lane & 7, gg = lane >> 3;
    const uint32_t aAddrHi = sb + SM_A + (uint32_t)(m0 + lr + (gg & 1) * 8) * RSTRIDE + (gg >> 1) * 16;
    // B-frag lane addressing: groups = {hi k0, hi k0+8, lo k0, lo k0+8}
    const uint32_t bOffLane = (uint32_t)lr * RSTRIDE + (gg & 1) * 16 + (gg >> 1) * 224;

    float cS[25];
    #pragma unroll
    for (int i = 0; i < 25; ++i) cS[i] = 0.f;
    float accLP = 0.f, accENT = 0.f;

    for (int t = 0; t < TT; ++t) {
        // gumbel inputs for epilogue threads
        float un[NOPSN];
        if (tid < MROWS) {
            const float* up = upt + ((size_t)t * BB + blockIdx.x * MROWS + tid) * NOPSN;
            #pragma unroll
            for (int n = 0; n < NOPSN; ++n) un[n] = up[n];
        }

        __syncthreads();   // sync0: As holds h(t-1), sOps holds op(t-1)

        // per-row xW pointers
        const float *p0, *p1;
        if (t == 0) {
            p0 = g_xW0 + (size_t)(blockIdx.x * MROWS + R0l) * ZW;
            p1 = g_xW0 + (size_t)(blockIdx.x * MROWS + R1l) * ZW;
        } else {
            p0 = sEmbF + sOps[R0l] * ZW;
            p1 = sEmbF + sOps[R1l] * ZW;
        }

        // ---- load A fragments (h(t-1) hi/lo), 7 k-steps ----
        uint32_t ahi[28], alo[28];
        #pragma unroll
        for (int kk = 0; kk < 7; ++kk) {
            ldsm4(ahi[4 * kk], ahi[4 * kk + 1], ahi[4 * kk + 2], ahi[4 * kk + 3], aAddrHi + kk * 32);
            ldsm4(alo[4 * kk], alo[4 * kk + 1], alo[4 * kk + 2], alo[4 * kk + 3], aAddrHi + 224 + kk * 32);
        }
        __syncthreads();   // sync1: all A reads done; safe to overwrite As with h(t)

        float pl[NOPSN] = {0.f, 0.f, 0.f, 0.f, 0.f};

        #pragma unroll
        for (int jj = 0; jj < 25; ++jj) {
            const int n0 = 8 * (jbase + jj);
            const uint32_t bb = sb + SM_B + (uint32_t)n0 * RSTRIDE + bOffLane;
            // 3-pass split-precision accumulate (independent chains for ILP)
            float A0 = 0.f, A1 = 0.f, A2 = 0.f, A3 = 0.f;
            float B0 = 0.f, B1 = 0.f, B2 = 0.f, B3 = 0.f;
            float C0 = 0.f, C1 = 0.f, C2 = 0.f, C3 = 0.f;
            #pragma unroll
            for (int kk = 0; kk < 7; ++kk) {
                uint32_t bh0, bh1, bl0, bl1;
                ldsm4(bh0, bh1, bl0, bl1, bb + kk * 32);
                mma16816(A0, A1, A2, A3, ahi[4 * kk], ahi[4 * kk + 1], ahi[4 * kk + 2], ahi[4 * kk + 3], bh0, bh1);
                mma16816(B0, B1, B2, B3, ahi[4 * kk], ahi[4 * kk + 1], ahi[4 * kk + 2], ahi[4 * kk + 3], bl0, bl1);
                mma16816(C0, C1, C2, C3, alo[4 * kk], alo[4 * kk + 1], alo[4 * kk + 2], alo[4 * kk + 3], bh0, bh1);
            }
            const int col0 = n0 + 2 * cq;
            float z0 = (A0 + B0 + C0) + p0[col0];
            float z1 = (A1 + B1 + C1) + p0[col0 + 1];
            float z2 = (A2 + B2 + C2) + p1[col0];
            float z3 = (A3 + B3 + C3) + p1[col0 + 1];
            float o0 = __shfl_xor_sync(0xffffffffu, z0, 1);
            float o1 = __shfl_xor_sync(0xffffffffu, z1, 1);
            float o2 = __shfl_xor_sync(0xffffffffu, z2, 1);
            float o3 = __shfl_xor_sync(0xffffffffu, z3, 1);
            // even lane: row R0 gates (i,f)=own(z0,z1), (c,o)=partner(o0,o1)
            // odd  lane: row R1 gates (i,f)=partner(o2,o3), (c,o)=own(z2,z3)
            float zi = even ? z0 : o2;
            float zf = even ? z1 : o3;
            float zc = even ? o0 : z2;
            float zo = even ? o1 : z3;
            float cn = fsig(zf) * cS[jj] + fsig(zi) * tanha(zc);
            cS[jj] = cn;
            float hn = fsig(zo) * tanha(cn);
            const int u = 2 * (jbase + jj) + (cq >> 1);
            const int myrow = even ? R0l : R1l;
            __half hh = __float2half_rn(hn);
            __half hl = __float2half_rn(hn - __half2float(hh));
            *(__half*)(smb + SM_A + myrow * RSTRIDE + u * 2) = hh;
            *(__half*)(smb + SM_A + myrow * RSTRIDE + 224 + u * 2) = hl;
            const float* wp = sWops + u * NOPSN;
            pl[0] = fmaf(hn, wp[0], pl[0]);
            pl[1] = fmaf(hn, wp[1], pl[1]);
            pl[2] = fmaf(hn, wp[2], pl[2]);
            pl[3] = fmaf(hn, wp[3], pl[3]);
            pl[4] = fmaf(hn, wp[4], pl[4]);
        }

        // combine unit-partials within warp: lanes {4g,4g+2} -> row R0, {4g+1,4g+3} -> row R1
        #pragma unroll
        for (int n = 0; n < NOPSN; ++n)
            pl[n] += __shfl_xor_sync(0xffffffffu, pl[n], 2);
        if (cq < 2) {
            int rw = (cq == 0) ? R0l : R1l;
            #pragma unroll
            for (int n = 0; n < NOPSN; ++n)
                sPL[rw * 10 + nh * NOPSN + n] = pl[n];
        }
        __syncthreads();   // sync2: sPL + As(t) complete

        // ---- sampling / log-softmax epilogue (accurate libm, 64 threads) ----
        if (tid < MROWS) {
            int b = blockIdx.x * MROWS + tid;
            float lg[NOPSN];
            #pragma unroll
            for (int n = 0; n < NOPSN; ++n) {
                float s = sPL[tid * 10 + n] + sPL[tid * 10 + NOPSN + n];
                lg[n] = 1.5f * tanhf(s);
            }
            int op = 0;
            float best = 0.f, mx = lg[0], lsel = lg[0];
            #pragma unroll
            for (int n = 0; n < NOPSN; ++n) {
                float gum = -logf(-logf(un[n] + 1e-9f) + 1e-9f);
                float v = lg[n] + gum;
                if (n == 0) { best = v; }
                else if (v > best) { best = v; op = n; lsel = lg[n]; }
                if (lg[n] > mx) mx = lg[n];
            }
            float ss = 0.f;
            #pragma unroll
            for (int n = 0; n < NOPSN; ++n) ss += expf(lg[n] - mx);
            float lse = mx + logf(ss);
            float cur = lse - lsel;
            float ent = cur * expf(-cur);
            accLP += cur; accENT += ent;
            sOps[tid] = op;
            out[2 * (size_t)BB + (size_t)t * BB + b] = (float)op;
        }
    }

    if (tid < MROWS) {
        int b = blockIdx.x * MROWS + tid;
        out[b] = accLP;
        out[BB + b] = accENT;
    }
}

extern "C" void kernel_launch(void* const* d_in, const int* in_sizes, int n_in,
                              void* d_out, int out_size) {
    const float* x0  = (const float*)d_in[0];
    const float* Wx  = (const float*)d_in[1];
    const float* Wh  = (const float*)d_in[2];
    const float* Wop = (const float*)d_in[3];
    const float* emb = (const float*)d_in[4];
    const float* u   = (const float*)d_in[5];
    float* out = (float*)d_out;

    cudaFuncSetAttribute(rnn_main, cudaFuncAttributeMaxDynamicSharedMemorySize, SM_TOTAL);

    embW_kernel<<<1, ZW>>>(emb, Wx);
    xw0_kernel<<<BB, 128>>>(x0, Wx);
    rnn_main<<<BB / MROWS, NTHREADS, SM_TOTAL>>>(Wh, Wop, u, out);
}

// round 12
// speedup vs baseline: 3.4086x; 1.0510x over previous
#include <cuda_runtime.h>
#include <cuda_fp16.h>
#include <cstdint>

#define BB 8192
#define HH 100
#define TT 512
#define NOPSN 5
#define ZW 400
#define MROWS 64
#define NTHREADS 256
#define RSTRIDE 464   // bytes/row: 112 f16 hi (224B) + 112 f16 lo (224B) + 16B pad

// smem byte offsets
#define SM_B    0                  // WhT hi/lo  [400][RSTRIDE]   = 185600
#define SM_A    185600             // h stage    [64][RSTRIDE]    = 29696
#define SM_EMB  215296             // float[6*400]                = 9600
#define SM_WOPS 224896             // float[500]                  = 2000
#define SM_PL   226896             // float[64*10]                = 2560
#define SM_OPS  229456             // int[64]                     = 256
#define SM_TOTAL 229712

__device__ float g_xW0[(size_t)BB * ZW];   // x0@Wx, permuted cols
__device__ float g_embW[6 * ZW];           // emb@Wx, permuted cols

// storage col j -> original col (j%4)*100 + j/4 (gate-interleaved)
__device__ __host__ __forceinline__ int permCol(int j) { return (j & 3) * 100 + (j >> 2); }

__device__ __forceinline__ float tanha(float x) {
    float y; asm("tanh.approx.f32 %0, %1;" : "=f"(y) : "f"(x)); return y;
}
__device__ __forceinline__ float fsig(float x) { return fmaf(0.5f, tanha(0.5f * x), 0.5f); }

__device__ __forceinline__ uint32_t smem_u32(const void* p) {
    uint32_t a;
    asm("{ .reg .u64 t; cvta.to.shared.u64 t, %1; cvt.u32.u64 %0, t; }" : "=r"(a) : "l"(p));
    return a;
}
__device__ __forceinline__ void ldsm4(uint32_t& r0, uint32_t& r1, uint32_t& r2, uint32_t& r3, uint32_t a) {
    asm volatile("ldmatrix.sync.aligned.m8n8.x4.shared.b16 {%0,%1,%2,%3}, [%4];"
                 : "=r"(r0), "=r"(r1), "=r"(r2), "=r"(r3) : "r"(a));
}
__device__ __forceinline__ void mma16816(float& d0, float& d1, float& d2, float& d3,
                                         uint32_t a0, uint32_t a1, uint32_t a2, uint32_t a3,
                                         uint32_t b0, uint32_t b1) {
    asm volatile("mma.sync.aligned.m16n8k16.row.col.f32.f16.f16.f32 "
                 "{%0,%1,%2,%3}, {%4,%5,%6,%7}, {%8,%9}, {%0,%1,%2,%3};"
                 : "+f"(d0), "+f"(d1), "+f"(d2), "+f"(d3)
                 : "r"(a0), "r"(a1), "r"(a2), "r"(a3), "r"(b0), "r"(b1));
}
__device__ __forceinline__ void pairbar(int id) {
    asm volatile("bar.sync %0, 64;" :: "r"(id) : "memory");
}

__global__ void embW_kernel(const float* __restrict__ emb, const float* __restrict__ Wx) {
    int j = threadIdx.x;
    if (j >= ZW) return;
    int pj = permCol(j);
    for (int e = 0; e < 6; ++e) {
        float acc = 0.f;
        #pragma unroll 4
        for (int k = 0; k < HH; ++k) acc = fmaf(emb[e * HH + k], Wx[k * ZW + pj], acc);
        g_embW[e * ZW + j] = acc;
    }
}

__global__ void xw0_kernel(const float* __restrict__ x0, const float* __restrict__ Wx) {
    __shared__ float xs[HH];
    int b = blockIdx.x;
    for (int i = threadIdx.x; i < HH; i += blockDim.x) xs[i] = x0[b * HH + i];
    __syncthreads();
    for (int j = threadIdx.x; j < ZW; j += blockDim.x) {
        int pj = permCol(j);
        float acc = 0.f;
        #pragma unroll 4
        for (int k = 0; k < HH; ++k) acc = fmaf(xs[k], Wx[k * ZW + pj], acc);
        g_xW0[(size_t)b * ZW + j] = acc;
    }
}

__global__ void __launch_bounds__(NTHREADS, 1)
rnn_main(const float* __restrict__ Wh, const float* __restrict__ Wops,
         const float* __restrict__ upt, float* __restrict__ out)
{
    extern __shared__ char smb[];
    const uint32_t sb = smem_u32(smb);
    float* sEmbF = (float*)(smb + SM_EMB);
    float* sWops = (float*)(smb + SM_WOPS);
    float* sPL   = (float*)(smb + SM_PL);
    int*   sOps  = (int*)(smb + SM_OPS);

    const int tid = threadIdx.x, wid = tid >> 5, lane = tid & 31;

    // ---- one-time init: B = Wh^T as f16 hi/lo, gate-interleaved n, K padded to 112 ----
    for (int idx = tid; idx < 400 * 112; idx += NTHREADS) {
        int n = idx / 112, k = idx - n * 112;
        float w = (k < HH) ? Wh[k * ZW + permCol(n)] : 0.f;
        __half hh = __float2half_rn(w);
        __half hl = __float2half_rn(w - __half2float(hh));
        *(__half*)(smb + SM_B + n * RSTRIDE + k * 2) = hh;
        *(__half*)(smb + SM_B + n * RSTRIDE + 224 + k * 2) = hl;
    }
    // zero A stage (h(-1) = 0, incl. k-pad 100..111)
    for (int i = tid; i < (MROWS * RSTRIDE) / 4; i += NTHREADS)
        ((uint32_t*)(smb + SM_A))[i] = 0u;
    for (int i = tid; i < 6 * ZW; i += NTHREADS) sEmbF[i] = g_embW[i];
    for (int i = tid; i < HH * NOPSN; i += NTHREADS) sWops[i] = Wops[i];
    __syncthreads();

    const int mt = wid & 3, nh = wid >> 2;
    const int gr = lane >> 2, cq = lane & 3;
    const bool even = ((lane & 1) == 0);
    const int m0 = mt * 16;
    const int R0l = m0 + gr, R1l = R0l + 8;
    const int jbase = nh * 25;
    const int barid = 1 + mt;
    const bool epi = (nh == 0) && (lane < 16);   // this lane runs the epilogue for row m0+lane
    const int erow = m0 + (lane & 15);

    // A-frag lane addressing (ldmatrix x4 groups)
    const int lr = lane & 7, gg = lane >> 3;
    const uint32_t aAddrHi = sb + SM_A + (uint32_t)(m0 + lr + (gg & 1) * 8) * RSTRIDE + (gg >> 1) * 16;
    // B-frag lane addressing: groups = {hi k0, hi k0+8, lo k0, lo k0+8}
    const uint32_t bOffLane = (uint32_t)lr * RSTRIDE + (gg & 1) * 16 + (gg >> 1) * 224;

    float cS[25];
    #pragma unroll
    for (int i = 0; i < 25; ++i) cS[i] = 0.f;
    float accLP = 0.f, accENT = 0.f;

    for (int t = 0; t < TT; ++t) {
        // gumbel inputs for this lane's epilogue row
        float un[NOPSN];
        if (epi) {
            const float* up = upt + ((size_t)t * BB + blockIdx.x * MROWS + erow) * NOPSN;
            #pragma unroll
            for (int n = 0; n < NOPSN; ++n) un[n] = up[n];
        }

        pairbar(barid);   // bar0: h(t-1) stage + sOps(t-1) stable for this slab

        // per-row xW pointers
        const float *p0, *p1;
        if (t == 0) {
            p0 = g_xW0 + (size_t)(blockIdx.x * MROWS + R0l) * ZW;
            p1 = g_xW0 + (size_t)(blockIdx.x * MROWS + R1l) * ZW;
        } else {
            p0 = sEmbF + sOps[R0l] * ZW;
            p1 = sEmbF + sOps[R1l] * ZW;
        }

        // ---- load A fragments (h(t-1) hi/lo), 7 k-steps ----
        uint32_t ahi[28], alo[28];
        #pragma unroll
        for (int kk = 0; kk < 7; ++kk) {
            ldsm4(ahi[4 * kk], ahi[4 * kk + 1], ahi[4 * kk + 2], ahi[4 * kk + 3], aAddrHi + kk * 32);
            ldsm4(alo[4 * kk], alo[4 * kk + 1], alo[4 * kk + 2], alo[4 * kk + 3], aAddrHi + 224 + kk * 32);
        }
        pairbar(barid);   // bar1: slab A reads done; safe to overwrite with h(t)

        float pl[NOPSN] = {0.f, 0.f, 0.f, 0.f, 0.f};

        #pragma unroll
        for (int jj = 0; jj < 25; ++jj) {
            const int n0 = 8 * (jbase + jj);
            const uint32_t bb = sb + SM_B + (uint32_t)n0 * RSTRIDE + bOffLane;
            // 3-pass split-precision accumulate (independent chains for ILP)
            float A0 = 0.f, A1 = 0.f, A2 = 0.f, A3 = 0.f;
            float B0 = 0.f, B1 = 0.f, B2 = 0.f, B3 = 0.f;
            float C0 = 0.f, C1 = 0.f, C2 = 0.f, C3 = 0.f;
            #pragma unroll
            for (int kk = 0; kk < 7; ++kk) {
                uint32_t bh0, bh1, bl0, bl1;
                ldsm4(bh0, bh1, bl0, bl1, bb + kk * 32);
                mma16816(A0, A1, A2, A3, ahi[4 * kk], ahi[4 * kk + 1], ahi[4 * kk + 2], ahi[4 * kk + 3], bh0, bh1);
                mma16816(B0, B1, B2, B3, ahi[4 * kk], ahi[4 * kk + 1], ahi[4 * kk + 2], ahi[4 * kk + 3], bl0, bl1);
                mma16816(C0, C1, C2, C3, alo[4 * kk], alo[4 * kk + 1], alo[4 * kk + 2], alo[4 * kk + 3], bh0, bh1);
            }
            const int col0 = n0 + 2 * cq;
            float z0 = (A0 + B0 + C0) + p0[col0];
            float z1 = (A1 + B1 + C1) + p0[col0 + 1];
            float z2 = (A2 + B2 + C2) + p1[col0];
            float z3 = (A3 + B3 + C3) + p1[col0 + 1];
            float o0 = __shfl_xor_sync(0xffffffffu, z0, 1);
            float o1 = __shfl_xor_sync(0xffffffffu, z1, 1);
            float o2 = __shfl_xor_sync(0xffffffffu, z2, 1);
            float o3 = __shfl_xor_sync(0xffffffffu, z3, 1);
            // even lane: row R0 gates (i,f)=own(z0,z1), (c,o)=partner(o0,o1)
            // odd  lane: row R1 gates (i,f)=partner(o2,o3), (c,o)=own(z2,z3)
            float zi = even ? z0 : o2;
            float zf = even ? z1 : o3;
            float zc = even ? o0 : z2;
            float zo = even ? o1 : z3;
            float cn = fsig(zf) * cS[jj] + fsig(zi) * tanha(zc);
            cS[jj] = cn;
            float hn = fsig(zo) * tanha(cn);
            const int u = 2 * (jbase + jj) + (cq >> 1);
            const int myrow = even ? R0l : R1l;
            __half hh = __float2half_rn(hn);
            __half hl = __float2half_rn(hn - __half2float(hh));
            *(__half*)(smb + SM_A + myrow * RSTRIDE + u * 2) = hh;
            *(__half*)(smb + SM_A + myrow * RSTRIDE + 224 + u * 2) = hl;
            const float* wp = sWops + u * NOPSN;
            pl[0] = fmaf(hn, wp[0], pl[0]);
            pl[1] = fmaf(hn, wp[1], pl[1]);
            pl[2] = fmaf(hn, wp[2], pl[2]);
            pl[3] = fmaf(hn, wp[3], pl[3]);
            pl[4] = fmaf(hn, wp[4], pl[4]);
        }

        // combine unit-partials within warp: lanes {4g,4g+2} -> row R0, {4g+1,4g+3} -> row R1
        #pragma unroll
        for (int n = 0; n < NOPSN; ++n)
            pl[n] += __shfl_xor_sync(0xffffffffu, pl[n], 2);
        if (cq < 2) {
            int rw = (cq == 0) ? R0l : R1l;
            #pragma unroll
            for (int n = 0; n < NOPSN; ++n)
                sPL[rw * 10 + nh * NOPSN + n] = pl[n];
        }
        pairbar(barid);   // bar2: slab sPL + h(t) complete

        // ---- sampling / log-softmax epilogue (accurate libm; 16 lanes per slab) ----
        if (epi) {
            int b = blockIdx.x * MROWS + erow;
            float lg[NOPSN];
            #pragma unroll
            for (int n = 0; n < NOPSN; ++n) {
                float s = sPL[erow * 10 + n] + sPL[erow * 10 + NOPSN + n];
                lg[n] = 1.5f * tanhf(s);
            }
            int op = 0;
            float best = 0.f, mx = lg[0], lsel = lg[0];
            #pragma unroll
            for (int n = 0; n < NOPSN; ++n) {
                float gum = -logf(-logf(un[n] + 1e-9f) + 1e-9f);
                float v = lg[n] + gum;
                if (n == 0) { best = v; }
                else if (v > best) { best = v; op = n; lsel = lg[n]; }
                if (lg[n] > mx) mx = lg[n];
            }
            float ss = 0.f;
            #pragma unroll
            for (int n = 0; n < NOPSN; ++n) ss += expf(lg[n] - mx);
            float lse = mx + logf(ss);
            float cur = lse - lsel;
            float ent = cur * expf(-cur);
            accLP += cur; accENT += ent;
            sOps[erow] = op;
            out[2 * (size_t)BB + (size_t)t * BB + b] = (float)op;
        }
    }

    if (epi) {
        int b = blockIdx.x * MROWS + erow;
        out[b] = accLP;
        out[BB + b] = accENT;
    }
}

extern "C" void kernel_launch(void* const* d_in, const int* in_sizes, int n_in,
                              void* d_out, int out_size) {
    const float* x0  = (const float*)d_in[0];
    const float* Wx  = (const float*)d_in[1];
    const float* Wh  = (const float*)d_in[2];
    const float* Wop = (const float*)d_in[3];
    const float* emb = (const float*)d_in[4];
    const float* u   = (const float*)d_in[5];
    float* out = (float*)d_out;

    cudaFuncSetAttribute(rnn_main, cudaFuncAttributeMaxDynamicSharedMemorySize, SM_TOTAL);

    embW_kernel<<<1, ZW>>>(emb, Wx);
    xw0_kernel<<<BB, 128>>>(x0, Wx);
    rnn_main<<<BB / MROWS, NTHREADS, SM_TOTAL>>>(Wh, Wop, u, out);
}

// round 13
// speedup vs baseline: 3.4793x; 1.0207x over previous
#include <cuda_runtime.h>
#include <cuda_fp16.h>
#include <cstdint>

#define BB 8192
#define HH 100
#define TT 512
#define NOPSN 5
#define ZW 400
#define MROWS 64
#define NTHREADS 256
#define RSTRIDE 464   // bytes/row: 112 f16 hi (224B) + 112 f16 lo (224B) + 16B pad

// smem byte offsets
#define SM_B    0                  // WhT hi/lo  [400][RSTRIDE]   = 185600
#define SM_A    185600             // h stage    [64][RSTRIDE]    = 29696
#define SM_EMB  215296             // float[6*400]                = 9600
#define SM_WOPS 224896             // float[500]                  = 2000
#define SM_PL   226896             // float[64*10]                = 2560
#define SM_OPS  229456             // int[64]                     = 256
#define SM_TOTAL 229712

__device__ float g_xW0[(size_t)BB * ZW];   // x0@Wx, permuted cols
__device__ float g_embW[6 * ZW];           // emb@Wx, permuted cols

// storage col j -> original col (j%4)*100 + j/4 (gate-interleaved)
__device__ __host__ __forceinline__ int permCol(int j) { return (j & 3) * 100 + (j >> 2); }

__device__ __forceinline__ float tanha(float x) {
    float y; asm("tanh.approx.f32 %0, %1;" : "=f"(y) : "f"(x)); return y;
}
__device__ __forceinline__ float fsig(float x) { return fmaf(0.5f, tanha(0.5f * x), 0.5f); }

__device__ __forceinline__ uint32_t smem_u32(const void* p) {
    uint32_t a;
    asm("{ .reg .u64 t; cvta.to.shared.u64 t, %1; cvt.u32.u64 %0, t; }" : "=r"(a) : "l"(p));
    return a;
}
__device__ __forceinline__ void ldsm4(uint32_t& r0, uint32_t& r1, uint32_t& r2, uint32_t& r3, uint32_t a) {
    asm volatile("ldmatrix.sync.aligned.m8n8.x4.shared.b16 {%0,%1,%2,%3}, [%4];"
                 : "=r"(r0), "=r"(r1), "=r"(r2), "=r"(r3) : "r"(a));
}
__device__ __forceinline__ void mma16816(float& d0, float& d1, float& d2, float& d3,
                                         uint32_t a0, uint32_t a1, uint32_t a2, uint32_t a3,
                                         uint32_t b0, uint32_t b1) {
    asm volatile("mma.sync.aligned.m16n8k16.row.col.f32.f16.f16.f32 "
                 "{%0,%1,%2,%3}, {%4,%5,%6,%7}, {%8,%9}, {%0,%1,%2,%3};"
                 : "+f"(d0), "+f"(d1), "+f"(d2), "+f"(d3)
                 : "r"(a0), "r"(a1), "r"(a2), "r"(a3), "r"(b0), "r"(b1));
}
// f16-accumulator variant: D,C are 2 x .f16x2 regs
__device__ __forceinline__ void mma16816h(uint32_t& d0, uint32_t& d1,
                                          uint32_t a0, uint32_t a1, uint32_t a2, uint32_t a3,
                                          uint32_t b0, uint32_t b1) {
    asm volatile("mma.sync.aligned.m16n8k16.row.col.f16.f16.f16.f16 "
                 "{%0,%1}, {%2,%3,%4,%5}, {%6,%7}, {%0,%1};"
                 : "+r"(d0), "+r"(d1)
                 : "r"(a0), "r"(a1), "r"(a2), "r"(a3), "r"(b0), "r"(b1));
}
__device__ __forceinline__ void pairbar(int id) {
    asm volatile("bar.sync %0, 64;" :: "r"(id) : "memory");
}
__device__ __forceinline__ float2 h2f2(uint32_t v) {
    __half2 h = *reinterpret_cast<__half2*>(&v);
    return __half22float2(h);
}

__global__ void embW_kernel(const float* __restrict__ emb, const float* __restrict__ Wx) {
    int j = threadIdx.x;
    if (j >= ZW) return;
    int pj = permCol(j);
    for (int e = 0; e < 6; ++e) {
        float acc = 0.f;
        #pragma unroll 4
        for (int k = 0; k < HH; ++k) acc = fmaf(emb[e * HH + k], Wx[k * ZW + pj], acc);
        g_embW[e * ZW + j] = acc;
    }
}

__global__ void xw0_kernel(const float* __restrict__ x0, const float* __restrict__ Wx) {
    __shared__ float xs[HH];
    int b = blockIdx.x;
    for (int i = threadIdx.x; i < HH; i += blockDim.x) xs[i] = x0[b * HH + i];
    __syncthreads();
    for (int j = threadIdx.x; j < ZW; j += blockDim.x) {
        int pj = permCol(j);
        float acc = 0.f;
        #pragma unroll 4
        for (int k = 0; k < HH; ++k) acc = fmaf(xs[k], Wx[k * ZW + pj], acc);
        g_xW0[(size_t)b * ZW + j] = acc;
    }
}

__global__ void __launch_bounds__(NTHREADS, 1)
rnn_main(const float* __restrict__ Wh, const float* __restrict__ Wops,
         const float* __restrict__ upt, float* __restrict__ out)
{
    extern __shared__ char smb[];
    const uint32_t sb = smem_u32(smb);
    float* sEmbF = (float*)(smb + SM_EMB);
    float* sWops = (float*)(smb + SM_WOPS);
    float* sPL   = (float*)(smb + SM_PL);
    int*   sOps  = (int*)(smb + SM_OPS);

    const int tid = threadIdx.x, wid = tid >> 5, lane = tid & 31;

    // ---- one-time init: B = Wh^T as f16 hi/lo, gate-interleaved n, K padded to 112 ----
    for (int idx = tid; idx < 400 * 112; idx += NTHREADS) {
        int n = idx / 112, k = idx - n * 112;
        float w = (k < HH) ? Wh[k * ZW + permCol(n)] : 0.f;
        __half hh = __float2half_rn(w);
        __half hl = __float2half_rn(w - __half2float(hh));
        *(__half*)(smb + SM_B + n * RSTRIDE + k * 2) = hh;
        *(__half*)(smb + SM_B + n * RSTRIDE + 224 + k * 2) = hl;
    }
    // zero A stage (h(-1) = 0, incl. k-pad 100..111)
    for (int i = tid; i < (MROWS * RSTRIDE) / 4; i += NTHREADS)
        ((uint32_t*)(smb + SM_A))[i] = 0u;
    for (int i = tid; i < 6 * ZW; i += NTHREADS) sEmbF[i] = g_embW[i];
    for (int i = tid; i < HH * NOPSN; i += NTHREADS) sWops[i] = Wops[i];
    __syncthreads();

    const int mt = wid & 3, nh = wid >> 2;
    const int gr = lane >> 2, cq = lane & 3;
    const bool even = ((lane & 1) == 0);
    const int m0 = mt * 16;
    const int R0l = m0 + gr, R1l = R0l + 8;
    const int jbase = nh * 25;
    const int barid = 1 + mt;
    // epilogue split: each warp of the pair handles 8 rows of its slab
    const bool epi = (lane < 8);
    const int erow = m0 + nh * 8 + (lane & 7);

    // A-frag lane addressing (ldmatrix x4 groups)
    const int lr = lane & 7, gg = lane >> 3;
    const uint32_t aAddrHi = sb + SM_A + (uint32_t)(m0 + lr + (gg & 1) * 8) * RSTRIDE + (gg >> 1) * 16;
    // B-frag lane addressing: groups = {hi k0, hi k0+8, lo k0, lo k0+8}
    const uint32_t bOffLane = (uint32_t)lr * RSTRIDE + (gg & 1) * 16 + (gg >> 1) * 224;

    float cS[25];
    #pragma unroll
    for (int i = 0; i < 25; ++i) cS[i] = 0.f;
    float accLP = 0.f, accENT = 0.f;

    for (int t = 0; t < TT; ++t) {
        // gumbel inputs for this lane's epilogue row
        float un[NOPSN];
        if (epi) {
            const float* up = upt + ((size_t)t * BB + blockIdx.x * MROWS + erow) * NOPSN;
            #pragma unroll
            for (int n = 0; n < NOPSN; ++n) un[n] = up[n];
        }

        pairbar(barid);   // bar0: h(t-1) stage + sOps(t-1) stable for this slab

        // per-row xW pointers
        const float *p0, *p1;
        if (t == 0) {
            p0 = g_xW0 + (size_t)(blockIdx.x * MROWS + R0l) * ZW;
            p1 = g_xW0 + (size_t)(blockIdx.x * MROWS + R1l) * ZW;
        } else {
            p0 = sEmbF + sOps[R0l] * ZW;
            p1 = sEmbF + sOps[R1l] * ZW;
        }

        // ---- load A fragments (h(t-1) hi/lo), 7 k-steps ----
        uint32_t ahi[28], alo[28];
        #pragma unroll
        for (int kk = 0; kk < 7; ++kk) {
            ldsm4(ahi[4 * kk], ahi[4 * kk + 1], ahi[4 * kk + 2], ahi[4 * kk + 3], aAddrHi + kk * 32);
            ldsm4(alo[4 * kk], alo[4 * kk + 1], alo[4 * kk + 2], alo[4 * kk + 3], aAddrHi + 224 + kk * 32);
        }
        pairbar(barid);   // bar1: slab A reads done; safe to overwrite with h(t)

        float pl[NOPSN] = {0.f, 0.f, 0.f, 0.f, 0.f};

        #pragma unroll
        for (int jj = 0; jj < 25; ++jj) {
            const int n0 = 8 * (jbase + jj);
            const uint32_t bb = sb + SM_B + (uint32_t)n0 * RSTRIDE + bOffLane;
            // pass A: f32 accumulate (full magnitude); passes B,C: f16 accumulate (corrections)
            float A0 = 0.f, A1 = 0.f, A2 = 0.f, A3 = 0.f;
            uint32_t Bh0 = 0u, Bh1 = 0u;   // ahi*blo, f16x2 accum {row gr}, {row gr+8}
            uint32_t Ch0 = 0u, Ch1 = 0u;   // alo*bhi
            #pragma unroll
            for (int kk = 0; kk < 7; ++kk) {
                uint32_t bh0, bh1, bl0, bl1;
                ldsm4(bh0, bh1, bl0, bl1, bb + kk * 32);
                mma16816(A0, A1, A2, A3, ahi[4 * kk], ahi[4 * kk + 1], ahi[4 * kk + 2], ahi[4 * kk + 3], bh0, bh1);
                mma16816h(Bh0, Bh1, ahi[4 * kk], ahi[4 * kk + 1], ahi[4 * kk + 2], ahi[4 * kk + 3], bl0, bl1);
                mma16816h(Ch0, Ch1, alo[4 * kk], alo[4 * kk + 1], alo[4 * kk + 2], alo[4 * kk + 3], bh0, bh1);
            }
            const int col0 = n0 + 2 * cq;
            float2 b0f = h2f2(Bh0), b1f = h2f2(Bh1);
            float2 c0f = h2f2(Ch0), c1f = h2f2(Ch1);
            float z0 = (A0 + b0f.x + c0f.x) + p0[col0];
            float z1 = (A1 + b0f.y + c0f.y) + p0[col0 + 1];
            float z2 = (A2 + b1f.x + c1f.x) + p1[col0];
            float z3 = (A3 + b1f.y + c1f.y) + p1[col0 + 1];
            float o0 = __shfl_xor_sync(0xffffffffu, z0, 1);
            float o1 = __shfl_xor_sync(0xffffffffu, z1, 1);
            float o2 = __shfl_xor_sync(0xffffffffu, z2, 1);
            float o3 = __shfl_xor_sync(0xffffffffu, z3, 1);
            // even lane: row R0 gates (i,f)=own(z0,z1), (c,o)=partner(o0,o1)
            // odd  lane: row R1 gates (i,f)=partner(o2,o3), (c,o)=own(z2,z3)
            float zi = even ? z0 : o2;
            float zf = even ? z1 : o3;
            float zc = even ? o0 : z2;
            float zo = even ? o1 : z3;
            float cn = fsig(zf) * cS[jj] + fsig(zi) * tanha(zc);
            cS[jj] = cn;
            float hn = fsig(zo) * tanha(cn);
            const int u = 2 * (jbase + jj) + (cq >> 1);
            const int myrow = even ? R0l : R1l;
            __half hh = __float2half_rn(hn);
            __half hl = __float2half_rn(hn - __half2float(hh));
            *(__half*)(smb + SM_A + myrow * RSTRIDE + u * 2) = hh;
            *(__half*)(smb + SM_A + myrow * RSTRIDE + 224 + u * 2) = hl;
            const float* wp = sWops + u * NOPSN;
            pl[0] = fmaf(hn, wp[0], pl[0]);
            pl[1] = fmaf(hn, wp[1], pl[1]);
            pl[2] = fmaf(hn, wp[2], pl[2]);
            pl[3] = fmaf(hn, wp[3], pl[3]);
            pl[4] = fmaf(hn, wp[4], pl[4]);
        }

        // combine unit-partials within warp: lanes {4g,4g+2} -> row R0, {4g+1,4g+3} -> row R1
        #pragma unroll
        for (int n = 0; n < NOPSN; ++n)
            pl[n] += __shfl_xor_sync(0xffffffffu, pl[n], 2);
        if (cq < 2) {
            int rw = (cq == 0) ? R0l : R1l;
            #pragma unroll
            for (int n = 0; n < NOPSN; ++n)
                sPL[rw * 10 + nh * NOPSN + n] = pl[n];
        }
        pairbar(barid);   // bar2: slab sPL + h(t) complete

        // ---- sampling / log-softmax epilogue (accurate libm; 8 lanes per warp) ----
        if (epi) {
            int b = blockIdx.x * MROWS + erow;
            float lg[NOPSN];
            #pragma unroll
            for (int n = 0; n < NOPSN; ++n) {
                float s = sPL[erow * 10 + n] + sPL[erow * 10 + NOPSN + n];
                lg[n] = 1.5f * tanhf(s);
            }
            int op = 0;
            float best = 0.f, mx = lg[0], lsel = lg[0];
            #pragma unroll
            for (int n = 0; n < NOPSN; ++n) {
                float gum = -logf(-logf(un[n] + 1e-9f) + 1e-9f);
                float v = lg[n] + gum;
                if (n == 0) { best = v; }
                else if (v > best) { best = v; op = n; lsel = lg[n]; }
                if (lg[n] > mx) mx = lg[n];
            }
            float ss = 0.f;
            #pragma unroll
            for (int n = 0; n < NOPSN; ++n) ss += expf(lg[n] - mx);
            float lse = mx + logf(ss);
            float cur = lse - lsel;
            float ent = cur * expf(-cur);
            accLP += cur; accENT += ent;
            sOps[erow] = op;
            out[2 * (size_t)BB + (size_t)t * BB + b] = (float)op;
        }
    }

    if (epi) {
        int b = blockIdx.x * MROWS + erow;
        out[b] = accLP;
        out[BB + b] = accENT;
    }
}

extern "C" void kernel_launch(void* const* d_in, const int* in_sizes, int n_in,
                              void* d_out, int out_size) {
    const float* x0  = (const float*)d_in[0];
    const float* Wx  = (const float*)d_in[1];
    const float* Wh  = (const float*)d_in[2];
    const float* Wop = (const float*)d_in[3];
    const float* emb = (const float*)d_in[4];
    const float* u   = (const float*)d_in[5];
    float* out = (float*)d_out;

    cudaFuncSetAttribute(rnn_main, cudaFuncAttributeMaxDynamicSharedMemorySize, SM_TOTAL);

    embW_kernel<<<1, ZW>>>(emb, Wx);
    xw0_kernel<<<BB, 128>>>(x0, Wx);
    rnn_main<<<BB / MROWS, NTHREADS, SM_TOTAL>>>(Wh, Wop, u, out);
}